// round 13
// baseline (speedup 1.0000x reference)
#include <cuda_runtime.h>

typedef unsigned long long ull;

#define BB 256
#define TT 2048

// layer-0 output: g_h1[(b*TT + t)*64 + dir*32 + cell]
__device__ float g_h1[(size_t)BB * TT * 64];

__device__ __forceinline__ float tanh_hw(float x) {
    float y;
    asm("tanh.approx.f32 %0, %1;" : "=f"(y) : "f"(x));
    return y;
}
__device__ __forceinline__ ull pack2(float lo, float hi) {
    ull r;
    asm("mov.b64 %0, {%1, %2};" : "=l"(r) : "f"(lo), "f"(hi));
    return r;
}
__device__ __forceinline__ void unpack2(ull v, float& lo, float& hi) {
    asm("mov.b64 {%0, %1}, %2;" : "=f"(lo), "=f"(hi) : "l"(v));
}
__device__ __forceinline__ ull ffma2(ull a, ull b, ull c) {
    ull d;
    asm("fma.rn.f32x2 %0, %1, %2, %3;" : "=l"(d) : "l"(a), "l"(b), "l"(c));
    return d;
}
__device__ __forceinline__ ull fadd2(ull a, ull b) {
    ull d;
    asm("add.rn.f32x2 %0, %1, %2;" : "=l"(d) : "l"(a), "l"(b));
    return d;
}

#define BARC(id) asm volatile("bar.sync %0, 96;" :: "r"(id) : "memory")

// ---------------------------------------------------------------------------
// Fused layer, 4 chains per 384-thread block (12 warps), 128 blocks (1/SM).
//   wid 0-3  : producer{i,f} for chain (wid&3)
//   wid 4-7  : producer{g,o} for chain (wid&3)
//   wid 8-11 : consumer      for chain (wid&3)
// Rounds of 8 steps; 16-slot xg/x rings; one named barrier per round.
// Consumer path surgery: xg added in the combine (its LDS hides under the
// ffma issue window), no __syncwarp (converged warp, aliasing-ordered smem).
// Sigmoid 0.5 input scale folded into weights/biases for gates i,f,o.
// ---------------------------------------------------------------------------
template<bool L0>
__global__ __launch_bounds__(384, 1)
void lstm_layer(const float* __restrict__ oseq,   // [B,T,16] (L0)
                const float* __restrict__ iseq,   // [B,T,16] (L0)
                const float* __restrict__ Wih,    // [2,128,F]
                const float* __restrict__ Whh,    // [2,128,32]
                const float* __restrict__ bih,    // [2,128]
                const float* __restrict__ bhh,    // [2,128]
                float* __restrict__ outp)         // L1: d_out [B,T,64]
{
    constexpr int F  = L0 ? 32 : 64;
    constexpr int RS = 8;                // steps per round
    constexpr int NR = TT / RS;          // rounds
    const int dir   = blockIdx.y;
    const int wid   = threadIdx.x >> 5;
    const int lane  = threadIdx.x & 31;
    const int chain = wid & 3;
    const int role  = wid >> 2;          // 0: prod{i,f}, 1: prod{g,o}, 2: consumer
    const int b     = blockIdx.x * 4 + chain;
    const int barid = chain + 1;

    __shared__ __align__(16) float ring[4][16][32][4];    // [chain][slot][cell][gate]
    __shared__ __align__(16) float xring[4][2][16][F];    // [chain][pw][slot][feat]
    __shared__ __align__(16) float h_sh[4][32];

    if (role == 2) {
        // ========================= consumer =========================
        ull w[4][16];
        #pragma unroll
        for (int g = 0; g < 4; g++) {
            const float2* p = (const float2*)(Whh + (size_t)(dir * 128 + g * 32 + lane) * 32);
            const float sc = (g == 2) ? 1.0f : 0.5f;
            #pragma unroll
            for (int k = 0; k < 16; k++) {
                const float2 v = p[k];
                w[g][k] = pack2(v.x * sc, v.y * sc);
            }
        }
        h_sh[chain][lane] = 0.0f;
        float c = 0.0f;
        __syncwarp();

        BARC(barid);   // round 0 produced

        float* const hout = L0 ? g_h1 : outp;
        const size_t orow = (size_t)b * TT;
        const int ocol = dir * 32 + lane;

        for (int r = 0; r < NR; r++) {
            #pragma unroll 2
            for (int j = 0; j < RS; j++) {
                const int ss = r * RS + j;

                // h loads first (true dependency), xg load issued after and
                // consumed only in the combine -> latency hidden by ffma issue
                const ulonglong2* hp = (const ulonglong2*)h_sh[chain];
                const float4 xg4 = *(const float4*)&ring[chain][ss & 15][lane][0];

                ull aA0 = 0, aB0 = 0, aA1 = 0, aB1 = 0;
                ull aA2 = 0, aB2 = 0, aA3 = 0, aB3 = 0;
                #pragma unroll
                for (int k = 0; k < 8; k++) {
                    const ulonglong2 hv = hp[k];
                    aA0 = ffma2(w[0][2 * k], hv.x, aA0); aB0 = ffma2(w[0][2 * k + 1], hv.y, aB0);
                    aA1 = ffma2(w[1][2 * k], hv.x, aA1); aB1 = ffma2(w[1][2 * k + 1], hv.y, aB1);
                    aA2 = ffma2(w[2][2 * k], hv.x, aA2); aB2 = ffma2(w[2][2 * k + 1], hv.y, aB2);
                    aA3 = ffma2(w[3][2 * k], hv.x, aA3); aB3 = ffma2(w[3][2 * k + 1], hv.y, aB3);
                }
                float lo, hi, gi, gf, gg, go;
                ull s0 = fadd2(aA0, aB0); unpack2(s0, lo, hi); gi = (lo + hi) + xg4.x;
                ull s1 = fadd2(aA1, aB1); unpack2(s1, lo, hi); gf = (lo + hi) + xg4.y;
                ull s2 = fadd2(aA2, aB2); unpack2(s2, lo, hi); gg = (lo + hi) + xg4.z;
                ull s3 = fadd2(aA3, aB3); unpack2(s3, lo, hi); go = (lo + hi) + xg4.w;

                const float fi = fmaf(tanh_hw(gi), 0.5f, 0.5f);
                const float ff = fmaf(tanh_hw(gf), 0.5f, 0.5f);
                const float tg = tanh_hw(gg);
                const float fo = fmaf(tanh_hw(go), 0.5f, 0.5f);
                c = fmaf(ff, c, fi * tg);
                const float h = fo * tanh_hw(c);

                // converged warp: in-order smem per warp; aliasing (same array)
                // prevents compiler reordering of next iteration's h loads
                h_sh[chain][lane] = h;

                const int t = dir ? (TT - 1 - ss) : ss;
                hout[(orow + t) * 64 + ocol] = h;
            }
            BARC(barid);
        }
    } else {
        // ========================= producer =========================
        const int pw = role;                   // 0: gates i,f   1: gates g,o
        const int r0 = pw * 64 + lane;         // i or g row
        const int r1 = pw * 64 + 32 + lane;    // f or o row
        const float sc0 = (pw == 0) ? 0.5f : 1.0f;
        const float sc1 = 0.5f;

        ull w0[F / 2], w1[F / 2];
        {
            const float2* p0 = (const float2*)(Wih + (size_t)(dir * 128 + r0) * F);
            const float2* p1 = (const float2*)(Wih + (size_t)(dir * 128 + r1) * F);
            #pragma unroll
            for (int k = 0; k < F / 2; k++) {
                const float2 a = p0[k], bv = p1[k];
                w0[k] = pack2(a.x * sc0, a.y * sc0);
                w1[k] = pack2(bv.x * sc1, bv.y * sc1);
            }
        }
        const float bias0 = (bih[dir * 128 + r0] + bhh[dir * 128 + r0]) * sc0;
        const float bias1 = (bih[dir * 128 + r1] + bhh[dir * 128 + r1]) * sc1;

        float* const myx = &xring[chain][pw][0][0];

        auto ldx = [&](int ss, float2& v) {
            ss = ss < TT - 1 ? ss : TT - 1;
            const int t = dir ? (TT - 1 - ss) : ss;
            if (L0) {
                if (lane < 16) v.x = oseq[((size_t)b * TT + t) * 16 + lane];
                else           v.x = iseq[((size_t)b * TT + (TT - 1 - t)) * 16 + (lane - 16)];
                v.y = 0.0f;
            } else {
                v = *(const float2*)(g_h1 + ((size_t)b * TT + t) * 64 + 2 * lane);
            }
        };
        auto stx = [&](int ss, const float2& v) {
            const int slot = ss & 15;
            if (L0) myx[slot * F + lane] = v.x;
            else    *(float2*)&myx[slot * F + 2 * lane] = v;
        };

        auto produce = [&](int ss) {
            const ulonglong2* xp = (const ulonglong2*)&myx[(ss & 15) * F];
            ull a0 = 0, c0 = 0, a1 = 0, c1 = 0;
            #pragma unroll
            for (int k = 0; k < F / 4; k++) {
                const ulonglong2 v = xp[k];
                a0 = ffma2(w0[2 * k],     v.x, a0);
                c0 = ffma2(w0[2 * k + 1], v.y, c0);
                a1 = ffma2(w1[2 * k],     v.x, a1);
                c1 = ffma2(w1[2 * k + 1], v.y, c1);
            }
            float lo, hi;
            float2 o;
            ull t0 = fadd2(a0, c0); unpack2(t0, lo, hi); o.x = (lo + hi) + bias0;
            ull t1 = fadd2(a1, c1); unpack2(t1, lo, hi); o.y = (lo + hi) + bias1;
            *(float2*)&ring[chain][ss & 15][lane][2 * pw] = o;
        };

        // prologue: x for steps 0..15 (rounds 0-1); produce round 0 (steps 0-7)
        {
            float2 v[16];
            #pragma unroll
            for (int j = 0; j < 16; j++) ldx(j, v[j]);
            #pragma unroll
            for (int j = 0; j < 16; j++) stx(j, v[j]);
            __syncwarp();
            #pragma unroll 2
            for (int j = 0; j < RS; j++) produce(j);
        }
        BARC(barid);

        for (int r = 0; r < NR; r++) {
            // 1) LDGs for round r+2's x (steps RS*r+16 .. +23, clamped)
            float2 pend[RS];
            #pragma unroll
            for (int j = 0; j < RS; j++) ldx(RS * r + 16 + j, pend[j]);

            // 2) produce round r+1 (LDS only)
            if (r + 1 < NR) {
                #pragma unroll 2
                for (int j = 0; j < RS; j++) produce(RS * (r + 1) + j);
            }

            // 3) commit arrived x (read next round)
            #pragma unroll
            for (int j = 0; j < RS; j++) stx(RS * r + 16 + j, pend[j]);
            __syncwarp();

            BARC(barid);
        }
    }
}

extern "C" void kernel_launch(void* const* d_in, const int* in_sizes, int n_in,
                              void* d_out, int out_size) {
    (void)in_sizes; (void)n_in; (void)out_size;
    const float* oseq = (const float*)d_in[0];
    const float* iseq = (const float*)d_in[1];
    const float* Wih0 = (const float*)d_in[2];
    const float* Whh0 = (const float*)d_in[3];
    const float* bih0 = (const float*)d_in[4];
    const float* bhh0 = (const float*)d_in[5];
    const float* Wih1 = (const float*)d_in[6];
    const float* Whh1 = (const float*)d_in[7];
    const float* bih1 = (const float*)d_in[8];
    const float* bhh1 = (const float*)d_in[9];
    float* out = (float*)d_out;

    lstm_layer<true ><<<dim3(64, 2), 384>>>(oseq, iseq, Wih0, Whh0, bih0, bhh0, nullptr);
    lstm_layer<false><<<dim3(64, 2), 384>>>(nullptr, nullptr, Wih1, Whh1, bih1, bhh1, out);
}

// round 14
// speedup vs baseline: 1.0672x; 1.0672x over previous
#include <cuda_runtime.h>

typedef unsigned long long ull;

#define BB 256
#define TT 2048

// layer-0 output: g_h1[(b*TT + t)*64 + dir*32 + cell]
__device__ float g_h1[(size_t)BB * TT * 64];

__device__ __forceinline__ float tanh_hw(float x) {
    float y;
    asm("tanh.approx.f32 %0, %1;" : "=f"(y) : "f"(x));
    return y;
}
__device__ __forceinline__ ull pack2(float lo, float hi) {
    ull r;
    asm("mov.b64 %0, {%1, %2};" : "=l"(r) : "f"(lo), "f"(hi));
    return r;
}
__device__ __forceinline__ void unpack2(ull v, float& lo, float& hi) {
    asm("mov.b64 {%0, %1}, %2;" : "=f"(lo), "=f"(hi) : "l"(v));
}
__device__ __forceinline__ ull ffma2(ull a, ull b, ull c) {
    ull d;
    asm("fma.rn.f32x2 %0, %1, %2, %3;" : "=l"(d) : "l"(a), "l"(b), "l"(c));
    return d;
}
__device__ __forceinline__ ull fadd2(ull a, ull b) {
    ull d;
    asm("add.rn.f32x2 %0, %1, %2;" : "=l"(d) : "l"(a), "l"(b));
    return d;
}

#define BARC(id) asm volatile("bar.sync %0, 96;" :: "r"(id) : "memory")

// ---------------------------------------------------------------------------
// Fused layer, 4 chains per 384-thread block (12 warps), 128 blocks (1/SM).
//   wid 0-3  : producer{i,f} for chain (wid&3)
//   wid 4-7  : producer{g,o} for chain (wid&3)
//   wid 8-11 : consumer      for chain (wid&3)
// Rounds of 4 steps; 8-slot rings; one named barrier (chain+1, 96) per round.
// CONSUMER h-EXCHANGE VIA SHUFFLES: h stays in registers; per step the 32
// cell values are broadcast with shfl.sync pairs interleaved into the ffma2
// stream. No h smem, no STS->LDS round-trip on the recurrence critical path.
// Sigmoid 0.5 input scale folded into weights/biases for gates i,f,o.
// ---------------------------------------------------------------------------
template<bool L0>
__global__ __launch_bounds__(384, 1)
void lstm_layer(const float* __restrict__ oseq,   // [B,T,16] (L0)
                const float* __restrict__ iseq,   // [B,T,16] (L0)
                const float* __restrict__ Wih,    // [2,128,F]
                const float* __restrict__ Whh,    // [2,128,32]
                const float* __restrict__ bih,    // [2,128]
                const float* __restrict__ bhh,    // [2,128]
                float* __restrict__ outp)         // L1: d_out [B,T,64]
{
    constexpr int F  = L0 ? 32 : 64;
    constexpr int RS = 4;                // steps per round
    constexpr int NR = TT / RS;          // rounds
    const int dir   = blockIdx.y;
    const int wid   = threadIdx.x >> 5;
    const int lane  = threadIdx.x & 31;
    const int chain = wid & 3;
    const int role  = wid >> 2;          // 0: prod{i,f}, 1: prod{g,o}, 2: consumer
    const int b     = blockIdx.x * 4 + chain;
    const int barid = chain + 1;

    __shared__ __align__(16) float ring[4][8][32][4];    // [chain][slot][cell][gate]
    __shared__ __align__(16) float xring[4][2][8][F];    // [chain][pw][slot][feat]

    if (role == 2) {
        // ========================= consumer =========================
        // w[g][k] = (W_hh[g*32+lane][2k], [2k+1]) * (0.5 for i,f,o; 1 for g)
        ull w[4][16];
        #pragma unroll
        for (int g = 0; g < 4; g++) {
            const float2* p = (const float2*)(Whh + (size_t)(dir * 128 + g * 32 + lane) * 32);
            const float sc = (g == 2) ? 1.0f : 0.5f;
            #pragma unroll
            for (int k = 0; k < 16; k++) {
                const float2 v = p[k];
                w[g][k] = pack2(v.x * sc, v.y * sc);
            }
        }
        float h = 0.0f, c = 0.0f;

        BARC(barid);   // round 0 produced

        float* const hout = L0 ? g_h1 : outp;
        const size_t orow = (size_t)b * TT;
        const int ocol = dir * 32 + lane;

        for (int r = 0; r < NR; r++) {
            #pragma unroll
            for (int j = 0; j < RS; j++) {
                const int ss = r * RS + j;
                const float4 xg4 = *(const float4*)&ring[chain][ss & 7][lane][0];

                ull a0 = pack2(xg4.x, 0.0f);
                ull a1 = pack2(xg4.y, 0.0f);
                ull a2 = pack2(xg4.z, 0.0f);
                ull a3 = pack2(xg4.w, 0.0f);

                #pragma unroll
                for (int k = 0; k < 16; k++) {
                    const float hl = __shfl_sync(0xffffffffu, h, 2 * k);
                    const float hh = __shfl_sync(0xffffffffu, h, 2 * k + 1);
                    const ull hv = pack2(hl, hh);
                    a0 = ffma2(w[0][k], hv, a0);
                    a1 = ffma2(w[1][k], hv, a1);
                    a2 = ffma2(w[2][k], hv, a2);
                    a3 = ffma2(w[3][k], hv, a3);
                }

                float lo, hi;
                unpack2(a0, lo, hi); const float gi = lo + hi;
                unpack2(a1, lo, hi); const float gf = lo + hi;
                unpack2(a2, lo, hi); const float gg = lo + hi;
                unpack2(a3, lo, hi); const float go = lo + hi;

                const float fi = fmaf(tanh_hw(gi), 0.5f, 0.5f);
                const float ff = fmaf(tanh_hw(gf), 0.5f, 0.5f);
                const float tg = tanh_hw(gg);
                const float fo = fmaf(tanh_hw(go), 0.5f, 0.5f);
                c = fmaf(ff, c, fi * tg);
                h = fo * tanh_hw(c);

                const int t = dir ? (TT - 1 - ss) : ss;
                hout[(orow + t) * 64 + ocol] = h;
            }
            BARC(barid);
        }
    } else {
        // ========================= producer (R12-proven) =========================
        const int pw = role;                   // 0: gates i,f   1: gates g,o
        const int r0 = pw * 64 + lane;         // i or g row
        const int r1 = pw * 64 + 32 + lane;    // f or o row
        const float sc0 = (pw == 0) ? 0.5f : 1.0f;
        const float sc1 = 0.5f;

        ull w0[F / 2], w1[F / 2];
        {
            const float2* p0 = (const float2*)(Wih + (size_t)(dir * 128 + r0) * F);
            const float2* p1 = (const float2*)(Wih + (size_t)(dir * 128 + r1) * F);
            #pragma unroll
            for (int k = 0; k < F / 2; k++) {
                const float2 a = p0[k], bv = p1[k];
                w0[k] = pack2(a.x * sc0, a.y * sc0);
                w1[k] = pack2(bv.x * sc1, bv.y * sc1);
            }
        }
        const float bias0 = (bih[dir * 128 + r0] + bhh[dir * 128 + r0]) * sc0;
        const float bias1 = (bih[dir * 128 + r1] + bhh[dir * 128 + r1]) * sc1;

        float* const myx = &xring[chain][pw][0][0];

        auto ldx = [&](int ss, float2& v) {
            ss = ss < TT - 1 ? ss : TT - 1;
            const int t = dir ? (TT - 1 - ss) : ss;
            if (L0) {
                if (lane < 16) v.x = oseq[((size_t)b * TT + t) * 16 + lane];
                else           v.x = iseq[((size_t)b * TT + (TT - 1 - t)) * 16 + (lane - 16)];
                v.y = 0.0f;
            } else {
                v = *(const float2*)(g_h1 + ((size_t)b * TT + t) * 64 + 2 * lane);
            }
        };
        auto stx = [&](int ss, const float2& v) {
            const int slot = ss & 7;
            if (L0) myx[slot * F + lane] = v.x;
            else    *(float2*)&myx[slot * F + 2 * lane] = v;
        };

        auto produce = [&](int ss) {
            const ulonglong2* xp = (const ulonglong2*)&myx[(ss & 7) * F];
            ull a0 = 0, c0 = 0, a1 = 0, c1 = 0;
            #pragma unroll
            for (int k = 0; k < F / 4; k++) {
                const ulonglong2 v = xp[k];
                a0 = ffma2(w0[2 * k],     v.x, a0);
                c0 = ffma2(w0[2 * k + 1], v.y, c0);
                a1 = ffma2(w1[2 * k],     v.x, a1);
                c1 = ffma2(w1[2 * k + 1], v.y, c1);
            }
            float lo, hi;
            float2 o;
            ull t0 = fadd2(a0, c0); unpack2(t0, lo, hi); o.x = (lo + hi) + bias0;
            ull t1 = fadd2(a1, c1); unpack2(t1, lo, hi); o.y = (lo + hi) + bias1;
            *(float2*)&ring[chain][ss & 7][lane][2 * pw] = o;
        };

        // prologue: x for steps 0..7; produce round 0 (steps 0-3)
        {
            float2 v[8];
            #pragma unroll
            for (int j = 0; j < 8; j++) ldx(j, v[j]);
            #pragma unroll
            for (int j = 0; j < 8; j++) stx(j, v[j]);
            __syncwarp();
            #pragma unroll
            for (int j = 0; j < 4; j++) produce(j);
        }
        BARC(barid);

        for (int r = 0; r < NR; r++) {
            // 1) LDGs for round r+2's x
            float2 pend[4];
            #pragma unroll
            for (int j = 0; j < 4; j++) ldx(4 * r + 8 + j, pend[j]);

            // 2) produce round r+1 (LDS only)
            if (r + 1 < NR) {
                #pragma unroll
                for (int j = 0; j < 4; j++) produce(4 * (r + 1) + j);
            }

            // 3) commit arrived x
            #pragma unroll
            for (int j = 0; j < 4; j++) stx(4 * r + 8 + j, pend[j]);
            __syncwarp();

            BARC(barid);
        }
    }
}

extern "C" void kernel_launch(void* const* d_in, const int* in_sizes, int n_in,
                              void* d_out, int out_size) {
    (void)in_sizes; (void)n_in; (void)out_size;
    const float* oseq = (const float*)d_in[0];
    const float* iseq = (const float*)d_in[1];
    const float* Wih0 = (const float*)d_in[2];
    const float* Whh0 = (const float*)d_in[3];
    const float* bih0 = (const float*)d_in[4];
    const float* bhh0 = (const float*)d_in[5];
    const float* Wih1 = (const float*)d_in[6];
    const float* Whh1 = (const float*)d_in[7];
    const float* bih1 = (const float*)d_in[8];
    const float* bhh1 = (const float*)d_in[9];
    float* out = (float*)d_out;

    lstm_layer<true ><<<dim3(64, 2), 384>>>(oseq, iseq, Wih0, Whh0, bih0, bhh0, nullptr);
    lstm_layer<false><<<dim3(64, 2), 384>>>(nullptr, nullptr, Wih1, Whh1, bih1, bhh1, out);
}

// round 15
// speedup vs baseline: 1.1538x; 1.0812x over previous
#include <cuda_runtime.h>
#include <cuda_fp16.h>

typedef unsigned long long ull;

#define BB 256
#define TT 2048

// layer-0 output: g_h1[(b*TT + t)*64 + dir*32 + cell]
__device__ float g_h1[(size_t)BB * TT * 64];

__device__ __forceinline__ float tanh_hw(float x) {
    float y;
    asm("tanh.approx.f32 %0, %1;" : "=f"(y) : "f"(x));
    return y;
}
__device__ __forceinline__ ull pack2(float lo, float hi) {
    ull r;
    asm("mov.b64 %0, {%1, %2};" : "=l"(r) : "f"(lo), "f"(hi));
    return r;
}
__device__ __forceinline__ void unpack2(ull v, float& lo, float& hi) {
    asm("mov.b64 {%0, %1}, %2;" : "=f"(lo), "=f"(hi) : "l"(v));
}
__device__ __forceinline__ ull ffma2(ull a, ull b, ull c) {
    ull d;
    asm("fma.rn.f32x2 %0, %1, %2, %3;" : "=l"(d) : "l"(a), "l"(b), "l"(c));
    return d;
}
__device__ __forceinline__ ull fadd2(ull a, ull b) {
    ull d;
    asm("add.rn.f32x2 %0, %1, %2;" : "=l"(d) : "l"(a), "l"(b));
    return d;
}

#define BARC(id) asm volatile("bar.sync %0, 96;" :: "r"(id) : "memory")

// ---------------------------------------------------------------------------
// Fused layer, 4 chains per 384-thread block (12 warps), 128 blocks (1/SM).
//   wid 0-3  : producer{i,f} for chain (wid&3)   -- fp16 HFMA2 x-side gates
//   wid 4-7  : producer{g,o} for chain (wid&3)   -- fp16 HFMA2 x-side gates
//   wid 8-11 : consumer      for chain (wid&3)   -- fp32 recurrence (R12)
// Rounds of 4 steps; 8-slot rings; one named barrier (chain+1, 96) per round.
// fp32 pipe is the roofline (16 MAC/cyc/SMSP); HFMA2 runs at 2x that rate, so
// the x-side GEMV moves to fp16 (inputs+weights fp16, cross-sum+bias fp32).
// Sigmoid 0.5 input scale folded into weights/biases for gates i,f,o.
// ---------------------------------------------------------------------------
template<bool L0>
__global__ __launch_bounds__(384, 1)
void lstm_layer(const float* __restrict__ oseq,   // [B,T,16] (L0)
                const float* __restrict__ iseq,   // [B,T,16] (L0)
                const float* __restrict__ Wih,    // [2,128,F]
                const float* __restrict__ Whh,    // [2,128,32]
                const float* __restrict__ bih,    // [2,128]
                const float* __restrict__ bhh,    // [2,128]
                float* __restrict__ outp)         // L1: d_out [B,T,64]
{
    constexpr int F  = L0 ? 32 : 64;
    constexpr int RS = 4;                // steps per round
    constexpr int NR = TT / RS;          // rounds
    const int dir   = blockIdx.y;
    const int wid   = threadIdx.x >> 5;
    const int lane  = threadIdx.x & 31;
    const int chain = wid & 3;
    const int role  = wid >> 2;          // 0: prod{i,f}, 1: prod{g,o}, 2: consumer
    const int b     = blockIdx.x * 4 + chain;
    const int barid = chain + 1;

    __shared__ __align__(16) float  ring[4][8][32][4];    // [chain][slot][cell][gate]
    __shared__ __align__(16) __half xring[4][2][8][F];    // [chain][pw][slot][feat]

    if (role == 2) {
        // ========================= consumer (fp32, R12) =========================
        ull w[4][16];
        #pragma unroll
        for (int g = 0; g < 4; g++) {
            const float2* p = (const float2*)(Whh + (size_t)(dir * 128 + g * 32 + lane) * 32);
            const float sc = (g == 2) ? 1.0f : 0.5f;
            #pragma unroll
            for (int k = 0; k < 16; k++) {
                const float2 v = p[k];
                w[g][k] = pack2(v.x * sc, v.y * sc);
            }
        }
        __shared__ __align__(16) float h_sh[4][32];
        h_sh[chain][lane] = 0.0f;
        float c = 0.0f;
        __syncwarp();

        BARC(barid);   // round 0 produced

        float* const hout = L0 ? g_h1 : outp;
        const size_t orow = (size_t)b * TT;
        const int ocol = dir * 32 + lane;

        for (int r = 0; r < NR; r++) {
            #pragma unroll
            for (int j = 0; j < RS; j++) {
                const int ss = r * RS + j;
                const float4 xg4 = *(const float4*)&ring[chain][ss & 7][lane][0];

                const ulonglong2* hp = (const ulonglong2*)h_sh[chain];
                ull aA0 = pack2(xg4.x, 0.0f), aB0 = 0ull;
                ull aA1 = pack2(xg4.y, 0.0f), aB1 = 0ull;
                ull aA2 = pack2(xg4.z, 0.0f), aB2 = 0ull;
                ull aA3 = pack2(xg4.w, 0.0f), aB3 = 0ull;
                #pragma unroll
                for (int k = 0; k < 8; k++) {
                    const ulonglong2 hv = hp[k];
                    aA0 = ffma2(w[0][2 * k], hv.x, aA0); aB0 = ffma2(w[0][2 * k + 1], hv.y, aB0);
                    aA1 = ffma2(w[1][2 * k], hv.x, aA1); aB1 = ffma2(w[1][2 * k + 1], hv.y, aB1);
                    aA2 = ffma2(w[2][2 * k], hv.x, aA2); aB2 = ffma2(w[2][2 * k + 1], hv.y, aB2);
                    aA3 = ffma2(w[3][2 * k], hv.x, aA3); aB3 = ffma2(w[3][2 * k + 1], hv.y, aB3);
                }
                float lo, hi, gi, gf, gg, go;
                ull s0 = fadd2(aA0, aB0); unpack2(s0, lo, hi); gi = lo + hi;
                ull s1 = fadd2(aA1, aB1); unpack2(s1, lo, hi); gf = lo + hi;
                ull s2 = fadd2(aA2, aB2); unpack2(s2, lo, hi); gg = lo + hi;
                ull s3 = fadd2(aA3, aB3); unpack2(s3, lo, hi); go = lo + hi;

                const float fi = fmaf(tanh_hw(gi), 0.5f, 0.5f);
                const float ff = fmaf(tanh_hw(gf), 0.5f, 0.5f);
                const float tg = tanh_hw(gg);
                const float fo = fmaf(tanh_hw(go), 0.5f, 0.5f);
                c = fmaf(ff, c, fi * tg);
                const float h = fo * tanh_hw(c);

                h_sh[chain][lane] = h;
                __syncwarp();

                const int t = dir ? (TT - 1 - ss) : ss;
                hout[(orow + t) * 64 + ocol] = h;
            }
            BARC(barid);
        }
    } else {
        // ========================= producer (fp16 HFMA2) =========================
        const int pw = role;                   // 0: gates i,f   1: gates g,o
        const int r0 = pw * 64 + lane;         // i or g row
        const int r1 = pw * 64 + 32 + lane;    // f or o row
        const float sc0 = (pw == 0) ? 0.5f : 1.0f;
        const float sc1 = 0.5f;

        __half2 w0h[F / 2], w1h[F / 2];
        {
            const float2* p0 = (const float2*)(Wih + (size_t)(dir * 128 + r0) * F);
            const float2* p1 = (const float2*)(Wih + (size_t)(dir * 128 + r1) * F);
            #pragma unroll
            for (int k = 0; k < F / 2; k++) {
                const float2 a = p0[k], bv = p1[k];
                w0h[k] = __floats2half2_rn(a.x * sc0, a.y * sc0);
                w1h[k] = __floats2half2_rn(bv.x * sc1, bv.y * sc1);
            }
        }
        const float bias0 = (bih[dir * 128 + r0] + bhh[dir * 128 + r0]) * sc0;
        const float bias1 = (bih[dir * 128 + r1] + bhh[dir * 128 + r1]) * sc1;

        __half* const myx = &xring[chain][pw][0][0];

        auto ldx = [&](int ss, float2& v) {
            ss = ss < TT - 1 ? ss : TT - 1;
            const int t = dir ? (TT - 1 - ss) : ss;
            if (L0) {
                if (lane < 16) v.x = oseq[((size_t)b * TT + t) * 16 + lane];
                else           v.x = iseq[((size_t)b * TT + (TT - 1 - t)) * 16 + (lane - 16)];
                v.y = 0.0f;
            } else {
                v = *(const float2*)(g_h1 + ((size_t)b * TT + t) * 64 + 2 * lane);
            }
        };
        auto stx = [&](int ss, const float2& v) {
            const int slot = ss & 7;
            if (L0) myx[slot * F + lane] = __float2half_rn(v.x);
            else    *(__half2*)&myx[slot * F + 2 * lane] = __floats2half2_rn(v.x, v.y);
        };

        auto produce = [&](int ss) {
            const __half2* xp = (const __half2*)&myx[(ss & 7) * F];
            const __half2 z = __floats2half2_rn(0.0f, 0.0f);
            __half2 a0 = z, b0 = z, a1 = z, b1 = z;
            #pragma unroll
            for (int k = 0; k < F / 2; k += 2) {
                const __half2 x0 = xp[k], x1 = xp[k + 1];
                a0 = __hfma2(w0h[k],     x0, a0);
                b0 = __hfma2(w0h[k + 1], x1, b0);
                a1 = __hfma2(w1h[k],     x0, a1);
                b1 = __hfma2(w1h[k + 1], x1, b1);
            }
            float2 o;
            o.x = ((__low2float(a0) + __high2float(a0))
                 + (__low2float(b0) + __high2float(b0))) + bias0;
            o.y = ((__low2float(a1) + __high2float(a1))
                 + (__low2float(b1) + __high2float(b1))) + bias1;
            *(float2*)&ring[chain][ss & 7][lane][2 * pw] = o;
        };

        // prologue: x for steps 0..7; produce round 0 (steps 0-3)
        {
            float2 v[8];
            #pragma unroll
            for (int j = 0; j < 8; j++) ldx(j, v[j]);
            #pragma unroll
            for (int j = 0; j < 8; j++) stx(j, v[j]);
            __syncwarp();
            #pragma unroll
            for (int j = 0; j < 4; j++) produce(j);
        }
        BARC(barid);

        for (int r = 0; r < NR; r++) {
            // 1) LDGs for round r+2's x
            float2 pend[4];
            #pragma unroll
            for (int j = 0; j < 4; j++) ldx(4 * r + 8 + j, pend[j]);

            // 2) produce round r+1 (LDS only)
            if (r + 1 < NR) {
                #pragma unroll
                for (int j = 0; j < 4; j++) produce(4 * (r + 1) + j);
            }

            // 3) commit arrived x
            #pragma unroll
            for (int j = 0; j < 4; j++) stx(4 * r + 8 + j, pend[j]);
            __syncwarp();

            BARC(barid);
        }
    }
}

extern "C" void kernel_launch(void* const* d_in, const int* in_sizes, int n_in,
                              void* d_out, int out_size) {
    (void)in_sizes; (void)n_in; (void)out_size;
    const float* oseq = (const float*)d_in[0];
    const float* iseq = (const float*)d_in[1];
    const float* Wih0 = (const float*)d_in[2];
    const float* Whh0 = (const float*)d_in[3];
    const float* bih0 = (const float*)d_in[4];
    const float* bhh0 = (const float*)d_in[5];
    const float* Wih1 = (const float*)d_in[6];
    const float* Whh1 = (const float*)d_in[7];
    const float* bih1 = (const float*)d_in[8];
    const float* bhh1 = (const float*)d_in[9];
    float* out = (float*)d_out;

    lstm_layer<true ><<<dim3(64, 2), 384>>>(oseq, iseq, Wih0, Whh0, bih0, bhh0, nullptr);
    lstm_layer<false><<<dim3(64, 2), 384>>>(nullptr, nullptr, Wih1, Whh1, bih1, bhh1, out);
}

// round 16
// speedup vs baseline: 1.2187x; 1.0563x over previous
#include <cuda_runtime.h>
#include <cuda_fp16.h>

typedef unsigned long long ull;

#define BB 256
#define TT 2048

// layer-0 output: g_h1[(b*TT + t)*64 + dir*32 + cell]
__device__ float g_h1[(size_t)BB * TT * 64];

__device__ __forceinline__ float tanh_hw(float x) {
    float y;
    asm("tanh.approx.f32 %0, %1;" : "=f"(y) : "f"(x));
    return y;
}
__device__ __forceinline__ ull pack2(float lo, float hi) {
    ull r;
    asm("mov.b64 %0, {%1, %2};" : "=l"(r) : "f"(lo), "f"(hi));
    return r;
}
__device__ __forceinline__ void unpack2(ull v, float& lo, float& hi) {
    asm("mov.b64 {%0, %1}, %2;" : "=f"(lo), "=f"(hi) : "l"(v));
}
__device__ __forceinline__ ull ffma2(ull a, ull b, ull c) {
    ull d;
    asm("fma.rn.f32x2 %0, %1, %2, %3;" : "=l"(d) : "l"(a), "l"(b), "l"(c));
    return d;
}
__device__ __forceinline__ ull fadd2(ull a, ull b) {
    ull d;
    asm("add.rn.f32x2 %0, %1, %2;" : "=l"(d) : "l"(a), "l"(b));
    return d;
}

#define BARC(id) asm volatile("bar.sync %0, 96;" :: "r"(id) : "memory")

struct alignas(16) H2x4 { __half2 h[4]; };

// ---------------------------------------------------------------------------
// Fused layer, 4 chains per 384-thread block (12 warps), 128 blocks (1/SM).
//   wid 0-3  : producer{i,f} for chain (wid&3)   -- fp16 HFMA2 x-side gates
//   wid 4-7  : producer{g,o} for chain (wid&3)   -- fp16 HFMA2 x-side gates
//   wid 8-11 : consumer      for chain (wid&3)   -- fp16 HFMA2 h-side,
//              fp32 cell state / activations / xg ring
// Rounds of 4 steps; 8-slot rings; one named barrier (chain+1, 96) per round.
// HFMA2 runs at 2x the fp32 MAC rate (rt2 vs f32x2 rt4): both the x-side
// GEMV and the h-side reduction use it. Accumulation split into 2 fp16
// chains per gate, combined + biased in fp32.
// Sigmoid 0.5 input scale folded into weights/biases for gates i,f,o.
// ---------------------------------------------------------------------------
template<bool L0>
__global__ __launch_bounds__(384, 1)
void lstm_layer(const float* __restrict__ oseq,   // [B,T,16] (L0)
                const float* __restrict__ iseq,   // [B,T,16] (L0)
                const float* __restrict__ Wih,    // [2,128,F]
                const float* __restrict__ Whh,    // [2,128,32]
                const float* __restrict__ bih,    // [2,128]
                const float* __restrict__ bhh,    // [2,128]
                float* __restrict__ outp)         // L1: d_out [B,T,64]
{
    constexpr int F  = L0 ? 32 : 64;
    constexpr int RS = 4;                // steps per round
    constexpr int NR = TT / RS;          // rounds
    const int dir   = blockIdx.y;
    const int wid   = threadIdx.x >> 5;
    const int lane  = threadIdx.x & 31;
    const int chain = wid & 3;
    const int role  = wid >> 2;          // 0: prod{i,f}, 1: prod{g,o}, 2: consumer
    const int b     = blockIdx.x * 4 + chain;
    const int barid = chain + 1;

    __shared__ __align__(16) float  ring[4][8][32][4];    // [chain][slot][cell][gate]
    __shared__ __align__(16) __half xring[4][2][8][F];    // [chain][pw][slot][feat]
    __shared__ __align__(16) __half h_sh[4][32];          // fp16 h exchange

    if (role == 2) {
        // ===== consumer: fp16 h-reduction, fp32 cell =====
        __half2 w[4][16];
        #pragma unroll
        for (int g = 0; g < 4; g++) {
            const float2* p = (const float2*)(Whh + (size_t)(dir * 128 + g * 32 + lane) * 32);
            const float sc = (g == 2) ? 1.0f : 0.5f;
            #pragma unroll
            for (int k = 0; k < 16; k++) {
                const float2 v = p[k];
                w[g][k] = __floats2half2_rn(v.x * sc, v.y * sc);
            }
        }
        h_sh[chain][lane] = __float2half_rn(0.0f);
        float c = 0.0f;
        __syncwarp();

        BARC(barid);   // round 0 produced

        float* const hout = L0 ? g_h1 : outp;
        const size_t orow = (size_t)b * TT;
        const int ocol = dir * 32 + lane;

        for (int r = 0; r < NR; r++) {
            #pragma unroll
            for (int j = 0; j < RS; j++) {
                const int ss = r * RS + j;
                const float4 xg4 = *(const float4*)&ring[chain][ss & 7][lane][0];

                const H2x4* hp = (const H2x4*)h_sh[chain];
                const __half2 z = __floats2half2_rn(0.0f, 0.0f);
                __half2 a0 = z, b0 = z, a1 = z, b1 = z;
                __half2 a2 = z, b2 = z, a3 = z, b3 = z;
                #pragma unroll
                for (int q = 0; q < 4; q++) {
                    const H2x4 blk = hp[q];
                    #pragma unroll
                    for (int jj = 0; jj < 4; jj += 2) {
                        const __half2 h0 = blk.h[jj], h1 = blk.h[jj + 1];
                        const int k = 4 * q + jj;
                        a0 = __hfma2(w[0][k], h0, a0); b0 = __hfma2(w[0][k + 1], h1, b0);
                        a1 = __hfma2(w[1][k], h0, a1); b1 = __hfma2(w[1][k + 1], h1, b1);
                        a2 = __hfma2(w[2][k], h0, a2); b2 = __hfma2(w[2][k + 1], h1, b2);
                        a3 = __hfma2(w[3][k], h0, a3); b3 = __hfma2(w[3][k + 1], h1, b3);
                    }
                }
                const __half2 s0 = __hadd2(a0, b0);
                const __half2 s1 = __hadd2(a1, b1);
                const __half2 s2 = __hadd2(a2, b2);
                const __half2 s3 = __hadd2(a3, b3);
                const float gi = (__low2float(s0) + __high2float(s0)) + xg4.x;
                const float gf = (__low2float(s1) + __high2float(s1)) + xg4.y;
                const float gg = (__low2float(s2) + __high2float(s2)) + xg4.z;
                const float go = (__low2float(s3) + __high2float(s3)) + xg4.w;

                const float fi = fmaf(tanh_hw(gi), 0.5f, 0.5f);
                const float ff = fmaf(tanh_hw(gf), 0.5f, 0.5f);
                const float tg = tanh_hw(gg);
                const float fo = fmaf(tanh_hw(go), 0.5f, 0.5f);
                c = fmaf(ff, c, fi * tg);
                const float h = fo * tanh_hw(c);

                h_sh[chain][lane] = __float2half_rn(h);
                __syncwarp();

                const int t = dir ? (TT - 1 - ss) : ss;
                hout[(orow + t) * 64 + ocol] = h;
            }
            BARC(barid);
        }
    } else {
        // ===== producer (fp16 HFMA2, R15-proven) =====
        const int pw = role;                   // 0: gates i,f   1: gates g,o
        const int r0 = pw * 64 + lane;         // i or g row
        const int r1 = pw * 64 + 32 + lane;    // f or o row
        const float sc0 = (pw == 0) ? 0.5f : 1.0f;
        const float sc1 = 0.5f;

        __half2 w0h[F / 2], w1h[F / 2];
        {
            const float2* p0 = (const float2*)(Wih + (size_t)(dir * 128 + r0) * F);
            const float2* p1 = (const float2*)(Wih + (size_t)(dir * 128 + r1) * F);
            #pragma unroll
            for (int k = 0; k < F / 2; k++) {
                const float2 a = p0[k], bv = p1[k];
                w0h[k] = __floats2half2_rn(a.x * sc0, a.y * sc0);
                w1h[k] = __floats2half2_rn(bv.x * sc1, bv.y * sc1);
            }
        }
        const float bias0 = (bih[dir * 128 + r0] + bhh[dir * 128 + r0]) * sc0;
        const float bias1 = (bih[dir * 128 + r1] + bhh[dir * 128 + r1]) * sc1;

        __half* const myx = &xring[chain][pw][0][0];

        auto ldx = [&](int ss, float2& v) {
            ss = ss < TT - 1 ? ss : TT - 1;
            const int t = dir ? (TT - 1 - ss) : ss;
            if (L0) {
                if (lane < 16) v.x = oseq[((size_t)b * TT + t) * 16 + lane];
                else           v.x = iseq[((size_t)b * TT + (TT - 1 - t)) * 16 + (lane - 16)];
                v.y = 0.0f;
            } else {
                v = *(const float2*)(g_h1 + ((size_t)b * TT + t) * 64 + 2 * lane);
            }
        };
        auto stx = [&](int ss, const float2& v) {
            const int slot = ss & 7;
            if (L0) myx[slot * F + lane] = __float2half_rn(v.x);
            else    *(__half2*)&myx[slot * F + 2 * lane] = __floats2half2_rn(v.x, v.y);
        };

        auto produce = [&](int ss) {
            const __half2* xp = (const __half2*)&myx[(ss & 7) * F];
            const __half2 z = __floats2half2_rn(0.0f, 0.0f);
            __half2 a0 = z, b0 = z, a1 = z, b1 = z;
            #pragma unroll
            for (int k = 0; k < F / 2; k += 2) {
                const __half2 x0 = xp[k], x1 = xp[k + 1];
                a0 = __hfma2(w0h[k],     x0, a0);
                b0 = __hfma2(w0h[k + 1], x1, b0);
                a1 = __hfma2(w1h[k],     x0, a1);
                b1 = __hfma2(w1h[k + 1], x1, b1);
            }
            float2 o;
            o.x = ((__low2float(a0) + __high2float(a0))
                 + (__low2float(b0) + __high2float(b0))) + bias0;
            o.y = ((__low2float(a1) + __high2float(a1))
                 + (__low2float(b1) + __high2float(b1))) + bias1;
            *(float2*)&ring[chain][ss & 7][lane][2 * pw] = o;
        };

        // prologue: x for steps 0..7; produce round 0 (steps 0-3)
        {
            float2 v[8];
            #pragma unroll
            for (int j = 0; j < 8; j++) ldx(j, v[j]);
            #pragma unroll
            for (int j = 0; j < 8; j++) stx(j, v[j]);
            __syncwarp();
            #pragma unroll
            for (int j = 0; j < 4; j++) produce(j);
        }
        BARC(barid);

        for (int r = 0; r < NR; r++) {
            // 1) LDGs for round r+2's x
            float2 pend[4];
            #pragma unroll
            for (int j = 0; j < 4; j++) ldx(4 * r + 8 + j, pend[j]);

            // 2) produce round r+1 (LDS only)
            if (r + 1 < NR) {
                #pragma unroll
                for (int j = 0; j < 4; j++) produce(4 * (r + 1) + j);
            }

            // 3) commit arrived x
            #pragma unroll
            for (int j = 0; j < 4; j++) stx(4 * r + 8 + j, pend[j]);
            __syncwarp();

            BARC(barid);
        }
    }
}

extern "C" void kernel_launch(void* const* d_in, const int* in_sizes, int n_in,
                              void* d_out, int out_size) {
    (void)in_sizes; (void)n_in; (void)out_size;
    const float* oseq = (const float*)d_in[0];
    const float* iseq = (const float*)d_in[1];
    const float* Wih0 = (const float*)d_in[2];
    const float* Whh0 = (const float*)d_in[3];
    const float* bih0 = (const float*)d_in[4];
    const float* bhh0 = (const float*)d_in[5];
    const float* Wih1 = (const float*)d_in[6];
    const float* Whh1 = (const float*)d_in[7];
    const float* bih1 = (const float*)d_in[8];
    const float* bhh1 = (const float*)d_in[9];
    float* out = (float*)d_out;

    lstm_layer<true ><<<dim3(64, 2), 384>>>(oseq, iseq, Wih0, Whh0, bih0, bhh0, nullptr);
    lstm_layer<false><<<dim3(64, 2), 384>>>(nullptr, nullptr, Wih1, Whh1, bih1, bhh1, out);
}

// round 17
// speedup vs baseline: 1.2260x; 1.0060x over previous
#include <cuda_runtime.h>
#include <cuda_fp16.h>

typedef unsigned long long ull;

#define BB 256
#define TT 2048

// layer-0 output: g_h1[(b*TT + t)*64 + dir*32 + cell]
__device__ float g_h1[(size_t)BB * TT * 64];

__device__ __forceinline__ float tanh_hw(float x) {
    float y;
    asm("tanh.approx.f32 %0, %1;" : "=f"(y) : "f"(x));
    return y;
}

#define BARC(id) asm volatile("bar.sync %0, 96;" :: "r"(id) : "memory")
#define CFENCE() asm volatile("" ::: "memory")

struct alignas(16) H2x4 { __half2 h[4]; };
struct alignas(8)  H2x2 { __half2 a, b; };

// ---------------------------------------------------------------------------
// Fused layer, 4 chains per 384-thread block (12 warps), 128 blocks (1/SM).
//   wid 0-3  : producer{i,f} for chain (wid&3)
//   wid 4-7  : producer{g,o} for chain (wid&3)
//   wid 8-11 : consumer      for chain (wid&3)
// Rounds of 4 steps; 8-slot rings; one named barrier (chain+1, 96) per round.
// LANE-PAIR = GATE-PAIR fp16 layout: w[k] = (Wg0[k], Wg1[k]); x and h are
// stored DUPLICATED as (v,v) half2 so accumulators finish holding the two
// gate values directly -- no per-gate horizontal reduction clutter.
// fp32: xg ring, activations, cell state. Sigmoid 0.5 folded into weights.
// ---------------------------------------------------------------------------
template<bool L0>
__global__ __launch_bounds__(384, 1)
void lstm_layer(const float* __restrict__ oseq,   // [B,T,16] (L0)
                const float* __restrict__ iseq,   // [B,T,16] (L0)
                const float* __restrict__ Wih,    // [2,128,F]
                const float* __restrict__ Whh,    // [2,128,32]
                const float* __restrict__ bih,    // [2,128]
                const float* __restrict__ bhh,    // [2,128]
                float* __restrict__ outp)         // L1: d_out [B,T,64]
{
    constexpr int F  = L0 ? 32 : 64;
    constexpr int RS = 4;                // steps per round
    constexpr int NR = TT / RS;          // rounds
    const int dir   = blockIdx.y;
    const int wid   = threadIdx.x >> 5;
    const int lane  = threadIdx.x & 31;
    const int chain = wid & 3;
    const int role  = wid >> 2;          // 0: prod{i,f}, 1: prod{g,o}, 2: consumer
    const int b     = blockIdx.x * 4 + chain;
    const int barid = chain + 1;

    __shared__ __align__(16) float   ring[4][8][32][4];   // [chain][slot][cell][gate] fp32
    __shared__ __align__(16) __half2 xring[4][2][8][F];   // duplicated (x,x) pairs
    __shared__ __align__(16) __half2 h_sh[4][32];         // duplicated (h,h)

    if (role == 2) {
        // ===== consumer: gate-pair fp16 h-reduction, fp32 cell =====
        // wif[k] = (Wi[k]*0.5, Wf[k]*0.5), wgo[k] = (Wg[k], Wo[k]*0.5)
        __half2 wif[32], wgo[32];
        {
            const float* pi = Whh + (size_t)(dir * 128 +  0 + lane) * 32;
            const float* pf = Whh + (size_t)(dir * 128 + 32 + lane) * 32;
            const float* pg = Whh + (size_t)(dir * 128 + 64 + lane) * 32;
            const float* po = Whh + (size_t)(dir * 128 + 96 + lane) * 32;
            #pragma unroll
            for (int k = 0; k < 32; k++) {
                wif[k] = __floats2half2_rn(pi[k] * 0.5f, pf[k] * 0.5f);
                wgo[k] = __floats2half2_rn(pg[k], po[k] * 0.5f);
            }
        }
        h_sh[chain][lane] = __floats2half2_rn(0.0f, 0.0f);
        float c = 0.0f;
        __syncwarp();

        BARC(barid);   // round 0 produced

        float* const hout = L0 ? g_h1 : outp;
        const size_t orow = (size_t)b * TT;
        const int ocol = dir * 32 + lane;

        for (int r = 0; r < NR; r++) {
            #pragma unroll
            for (int j = 0; j < RS; j++) {
                const int ss = r * RS + j;
                const float4 xg4 = *(const float4*)&ring[chain][ss & 7][lane][0];

                const H2x4* hp = (const H2x4*)h_sh[chain];
                const __half2 z = __floats2half2_rn(0.0f, 0.0f);
                __half2 aif0 = z, aif1 = z, aif2 = z, aif3 = z;
                __half2 ago0 = z, ago1 = z, ago2 = z, ago3 = z;
                #pragma unroll
                for (int q = 0; q < 8; q++) {
                    const H2x4 blk = hp[q];     // h cells 4q..4q+3, duplicated
                    const int k = 4 * q;
                    aif0 = __hfma2(wif[k],     blk.h[0], aif0);
                    aif1 = __hfma2(wif[k + 1], blk.h[1], aif1);
                    aif2 = __hfma2(wif[k + 2], blk.h[2], aif2);
                    aif3 = __hfma2(wif[k + 3], blk.h[3], aif3);
                    ago0 = __hfma2(wgo[k],     blk.h[0], ago0);
                    ago1 = __hfma2(wgo[k + 1], blk.h[1], ago1);
                    ago2 = __hfma2(wgo[k + 2], blk.h[2], ago2);
                    ago3 = __hfma2(wgo[k + 3], blk.h[3], ago3);
                }
                const __half2 sif = __hadd2(__hadd2(aif0, aif1), __hadd2(aif2, aif3));
                const __half2 sgo = __hadd2(__hadd2(ago0, ago1), __hadd2(ago2, ago3));
                const float2 fif = __half22float2(sif);   // (gi_h, gf_h)
                const float2 fgo = __half22float2(sgo);   // (gg_h, go_h)
                const float gi = fif.x + xg4.x;
                const float gf = fif.y + xg4.y;
                const float gg = fgo.x + xg4.z;
                const float go = fgo.y + xg4.w;

                const float fi = fmaf(tanh_hw(gi), 0.5f, 0.5f);
                const float ff = fmaf(tanh_hw(gf), 0.5f, 0.5f);
                const float tg = tanh_hw(gg);
                const float fo = fmaf(tanh_hw(go), 0.5f, 0.5f);
                c = fmaf(ff, c, fi * tg);
                const float h = fo * tanh_hw(c);

                h_sh[chain][lane] = __floats2half2_rn(h, h);
                CFENCE();   // same-warp smem wavefronts are program-ordered

                const int t = dir ? (TT - 1 - ss) : ss;
                hout[(orow + t) * 64 + ocol] = h;
            }
            BARC(barid);
        }
    } else {
        // ===== producer: gate-pair fp16 x-side GEMV =====
        const int pw = role;                   // 0: gates i,f   1: gates g,o
        const int r0 = pw * 64 + lane;         // i or g row
        const int r1 = pw * 64 + 32 + lane;    // f or o row
        const float sc0 = (pw == 0) ? 0.5f : 1.0f;
        const float sc1 = 0.5f;

        // wp[k] = (W_r0[k]*sc0, W_r1[k]*sc1), k = 0..F-1
        __half2 wp[F];
        {
            const float* p0 = Wih + (size_t)(dir * 128 + r0) * F;
            const float* p1 = Wih + (size_t)(dir * 128 + r1) * F;
            #pragma unroll
            for (int k = 0; k < F; k++)
                wp[k] = __floats2half2_rn(p0[k] * sc0, p1[k] * sc1);
        }
        const float bias0 = (bih[dir * 128 + r0] + bhh[dir * 128 + r0]) * sc0;
        const float bias1 = (bih[dir * 128 + r1] + bhh[dir * 128 + r1]) * sc1;

        __half2* const myx = &xring[chain][pw][0][0];

        auto ldx = [&](int ss, float2& v) {
            ss = ss < TT - 1 ? ss : TT - 1;
            const int t = dir ? (TT - 1 - ss) : ss;
            if (L0) {
                if (lane < 16) v.x = oseq[((size_t)b * TT + t) * 16 + lane];
                else           v.x = iseq[((size_t)b * TT + (TT - 1 - t)) * 16 + (lane - 16)];
                v.y = 0.0f;
            } else {
                v = *(const float2*)(g_h1 + ((size_t)b * TT + t) * 64 + 2 * lane);
            }
        };
        auto stx = [&](int ss, const float2& v) {
            const int slot = ss & 7;
            if (L0) {
                myx[slot * F + lane] = __floats2half2_rn(v.x, v.x);
            } else {
                H2x2 d;
                d.a = __floats2half2_rn(v.x, v.x);
                d.b = __floats2half2_rn(v.y, v.y);
                *(H2x2*)&myx[slot * F + 2 * lane] = d;
            }
        };

        auto produce = [&](int ss) {
            const H2x4* xp = (const H2x4*)&myx[(ss & 7) * F];
            const __half2 z = __floats2half2_rn(0.0f, 0.0f);
            __half2 a0 = z, a1 = z, a2 = z, a3 = z;
            #pragma unroll
            for (int q = 0; q < F / 4; q++) {
                const H2x4 blk = xp[q];
                const int k = 4 * q;
                a0 = __hfma2(wp[k],     blk.h[0], a0);
                a1 = __hfma2(wp[k + 1], blk.h[1], a1);
                a2 = __hfma2(wp[k + 2], blk.h[2], a2);
                a3 = __hfma2(wp[k + 3], blk.h[3], a3);
            }
            const __half2 s = __hadd2(__hadd2(a0, a1), __hadd2(a2, a3));
            const float2 f = __half22float2(s);
            float2 o;
            o.x = f.x + bias0;
            o.y = f.y + bias1;
            *(float2*)&ring[chain][ss & 7][lane][2 * pw] = o;
        };

        // prologue: x for steps 0..7; produce round 0 (steps 0-3)
        {
            float2 v[8];
            #pragma unroll
            for (int j = 0; j < 8; j++) ldx(j, v[j]);
            #pragma unroll
            for (int j = 0; j < 8; j++) stx(j, v[j]);
            __syncwarp();
            #pragma unroll
            for (int j = 0; j < 4; j++) produce(j);
        }
        BARC(barid);

        for (int r = 0; r < NR; r++) {
            // 1) LDGs for round r+2's x
            float2 pend[4];
            #pragma unroll
            for (int j = 0; j < 4; j++) ldx(4 * r + 8 + j, pend[j]);

            // 2) produce round r+1 (LDS only)
            if (r + 1 < NR) {
                #pragma unroll
                for (int j = 0; j < 4; j++) produce(4 * (r + 1) + j);
            }

            // 3) commit arrived x
            #pragma unroll
            for (int j = 0; j < 4; j++) stx(4 * r + 8 + j, pend[j]);
            CFENCE();

            BARC(barid);
        }
    }
}

extern "C" void kernel_launch(void* const* d_in, const int* in_sizes, int n_in,
                              void* d_out, int out_size) {
    (void)in_sizes; (void)n_in; (void)out_size;
    const float* oseq = (const float*)d_in[0];
    const float* iseq = (const float*)d_in[1];
    const float* Wih0 = (const float*)d_in[2];
    const float* Whh0 = (const float*)d_in[3];
    const float* bih0 = (const float*)d_in[4];
    const float* bhh0 = (const float*)d_in[5];
    const float* Wih1 = (const float*)d_in[6];
    const float* Whh1 = (const float*)d_in[7];
    const float* bih1 = (const float*)d_in[8];
    const float* bhh1 = (const float*)d_in[9];
    float* out = (float*)d_out;

    lstm_layer<true ><<<dim3(64, 2), 384>>>(oseq, iseq, Wih0, Whh0, bih0, bhh0, nullptr);
    lstm_layer<false><<<dim3(64, 2), 384>>>(nullptr, nullptr, Wih1, Whh1, bih1, bhh1, out);
}